// round 11
// baseline (speedup 1.0000x reference)
#include <cuda_runtime.h>
#include <cuda_bf16.h>
#include <cstdint>

// Problem: B=8, H=128, W=128, C=64, stride 2x2 max-unpool scatter-add.
// inputs  : [8,128,128,64] float32  -> 8,388,608 elements
// indices : [8,128,128,64] int32/int64 -> per-batch flat index into 256*256*64
// output  : [8,256,256,64] float32  -> 33,554,432 elements
static constexpr long long PER_BATCH_OUT = 256LL * 256 * 64;      // 2^22 (16MB)
static constexpr int NUM_BATCH = 8;
static constexpr int NSTAGE    = NUM_BATCH + 1;   // stage s: zero b=s, scatter b=s-1

static constexpr int BLOCK = 256;
// Roles: blocks [0,ZBLK) zero batch s via TMA bulk stores (LSU-free);
// blocks [ZBLK,GRID) scatter batch s-1 (4 elems/thread, 16B loads).
static constexpr int ZBLK  = 128;    // 128 blocks x 128KB = 16MB per stage
static constexpr int SBLK  = 1024;   // 1024*256*4 = 1,048,576 elems per stage
static constexpr int GRID  = ZBLK + SBLK;   // 1152 (single wave)

static constexpr int SMEM_TILE = 16384;      // 16KB zero tile per block
static constexpr int COPIES    = 131072 / SMEM_TILE;   // 8 bulk copies/block

// Runtime-detected layout flags (set by the probe block in stage 0).
__device__ int g_swap;   // 1 if d_in[0] is the indices buffer
__device__ int g_is64;   // 1 if indices are int64

// ---------------------------------------------------------------------------
// Stage kernel. Stage s zeroes batch s via TMA bulk stores from a zeroed SMEM
// tile (keeps the zero traffic OFF the LSU, which the scatter's REDG atomics
// saturate) and scatters batch s-1. Zero(b) one launch before scatter(b)
// keeps each 16MB atomic RMW working set L2-resident (no DRAM RMW); __ldcs on
// the streams protects those L2 lines. PDL: scatter loads issue pre-sync
// under the previous stage's atomic drain.
// ---------------------------------------------------------------------------
__global__ void __launch_bounds__(BLOCK) stage_kernel(
        const void* __restrict__ p0,
        const void* __restrict__ p1,
        float*      __restrict__ out,
        int stage) {

    cudaTriggerProgrammaticLaunchCompletion();

    __shared__ alignas(128) float4 ztile[SMEM_TILE / 16];

    if (blockIdx.x < ZBLK) {
        // ---- zero role: batch = stage, 128KB per block via 8x 16KB TMA ----
        if (stage >= NUM_BATCH) return;
        // Zero the SMEM tile (one-time; 4 STS.128/thread).
        const float4 zz = make_float4(0.f, 0.f, 0.f, 0.f);
        #pragma unroll
        for (int r = 0; r < 4; r++)
            ztile[threadIdx.x + r * BLOCK] = zz;
        // Make generic-proxy STS visible to the async (TMA) proxy.
        asm volatile("fence.proxy.async.shared::cta;" ::: "memory");
        __syncthreads();

        if (threadIdx.x == 0) {
            uint32_t saddr;
            asm("{ .reg .u64 t; cvta.to.shared.u64 t, %1; cvt.u32.u64 %0, t; }"
                : "=r"(saddr) : "l"(ztile));
            char* dst = reinterpret_cast<char*>(out + ((long long)stage << 22))
                        + (long long)blockIdx.x * (SMEM_TILE * COPIES);
            #pragma unroll
            for (int c = 0; c < COPIES; c++) {
                asm volatile(
                    "cp.async.bulk.global.shared::cta.bulk_group [%0], [%1], %2;"
                    :: "l"(dst + c * SMEM_TILE), "r"(saddr), "n"(SMEM_TILE)
                    : "memory");
            }
            asm volatile("cp.async.bulk.commit_group;" ::: "memory");
            asm volatile("cp.async.bulk.wait_group 0;" ::: "memory");
        }
        return;
    }

    // ---- scatter role (1024 blocks): batch = stage - 1, 4 elems/thread ----
    const long long s = (long long)(blockIdx.x - ZBLK);   // [0, 1024)

    if (stage == 0) {
        // Probe (one block): which buffer is indices, and are they int64?
        // Indices are small non-negative ints (< 2^22); normal float bits read
        // as int32 are ~1e9 or negative. int64 < 2^22 has odd words == 0.
        if (s != 0) return;
        const int* a = (const int*)p0;
        const int* b = (const int*)p1;
        int k = threadIdx.x;
        bool ok_a = (a[k] >= 0 && a[k] < (int)PER_BATCH_OUT);
        bool ok_b = (b[k] >= 0 && b[k] < (int)PER_BATCH_OUT);
        int ca = __syncthreads_count(ok_a);
        int cb = __syncthreads_count(ok_b);
        int swap = (ca > cb) ? 1 : 0;
        const int* idx = swap ? a : b;
        int nz = __syncthreads_count(idx[2 * k + 1] != 0);
        if (k == 0) { g_swap = swap; g_is64 = (nz == 0) ? 1 : 0; }
        return;
    }

    const long long b  = stage - 1;
    const long long u  = s * BLOCK + threadIdx.x;     // [0, 262144)
    const long long tg = (b << 18) + u;               // global 4-elem group id
    const long long i  = tg << 2;

    // Speculative flag read (stable after stage 0; deterministic on replays).
    int swap_s = __ldcg(&g_swap);
    int is64_s = __ldcg(&g_is64);
    const float* in  = (const float*)(swap_s ? p1 : p0);
    const void*  idx = swap_s ? p0 : p1;

    // Front-batched independent loads, pre-sync (hidden under prev drain).
    float4 v = __ldcs(reinterpret_cast<const float4*>(in + i));
    long long j0, j1, j2, j3;
    if (is64_s) {
        const longlong2 a0 = __ldcs(reinterpret_cast<const longlong2*>(idx) + tg * 2 + 0);
        const longlong2 a1 = __ldcs(reinterpret_cast<const longlong2*>(idx) + tg * 2 + 1);
        j0 = a0.x; j1 = a0.y; j2 = a1.x; j3 = a1.y;
    } else {
        const int4 a = __ldcs(reinterpret_cast<const int4*>(idx) + tg);
        j0 = a.x; j1 = a.y; j2 = a.z; j3 = a.w;
    }

    // Wait for the previous grid (zero(b) TMA stores + probe) to complete.
    cudaGridDependencySynchronize();

    // Re-check flags; reload if speculation was wrong (at most once ever).
    int swap_c = __ldcg(&g_swap);
    int is64_c = __ldcg(&g_is64);
    if (swap_c != swap_s || is64_c != is64_s) {
        const float* in2  = (const float*)(swap_c ? p1 : p0);
        const void*  idx2 = swap_c ? p0 : p1;
        v = __ldcs(reinterpret_cast<const float4*>(in2 + i));
        if (is64_c) {
            const longlong2 a0 = __ldcs(reinterpret_cast<const longlong2*>(idx2) + tg * 2 + 0);
            const longlong2 a1 = __ldcs(reinterpret_cast<const longlong2*>(idx2) + tg * 2 + 1);
            j0 = a0.x; j1 = a0.y; j2 = a1.x; j3 = a1.y;
        } else {
            const int4 a = __ldcs(reinterpret_cast<const int4*>(idx2) + tg);
            j0 = a.x; j1 = a.y; j2 = a.z; j3 = a.w;
        }
    }

    float* ob = out + (b << 22);   // batch base (all 4 elems same batch)
    if ((unsigned long long)j0 < (unsigned long long)PER_BATCH_OUT) atomicAdd(ob + j0, v.x);
    if ((unsigned long long)j1 < (unsigned long long)PER_BATCH_OUT) atomicAdd(ob + j1, v.y);
    if ((unsigned long long)j2 < (unsigned long long)PER_BATCH_OUT) atomicAdd(ob + j2, v.z);
    if ((unsigned long long)j3 < (unsigned long long)PER_BATCH_OUT) atomicAdd(ob + j3, v.w);
}

extern "C" void kernel_launch(void* const* d_in, const int* in_sizes, int n_in,
                              void* d_out, int out_size) {
    const void* p0 = d_in[0];
    const void* p1 = d_in[1];
    float* out = (float*)d_out;

    cudaLaunchAttribute attr[1];
    attr[0].id = cudaLaunchAttributeProgrammaticStreamSerialization;
    attr[0].val.programmaticStreamSerializationAllowed = 1;

    cudaLaunchConfig_t cfg = {};
    cfg.gridDim  = dim3(GRID, 1, 1);
    cfg.blockDim = dim3(BLOCK, 1, 1);
    cfg.stream = 0;
    cfg.attrs = attr;
    cfg.numAttrs = 1;

    // Stage 0: zero batch 0 + probe. Stages 1..7: zero b + scatter b-1.
    // Stage 8: scatter batch 7 only.
    for (int stage = 0; stage < NSTAGE; stage++) {
        cudaLaunchKernelEx(&cfg, stage_kernel, p0, p1, out, stage);
    }
}

// round 12
// speedup vs baseline: 1.1218x; 1.1218x over previous
#include <cuda_runtime.h>
#include <cuda_bf16.h>
#include <cstdint>

// Problem: B=8, H=128, W=128, C=64, stride 2x2 max-unpool scatter-add.
// inputs  : [8,128,128,64] float32  -> 8,388,608 elements
// indices : [8,128,128,64] int32/int64 -> per-batch flat index into 256*256*64
// output  : [8,256,256,64] float32  -> 33,554,432 elements
static constexpr long long PER_BATCH_OUT = 256LL * 256 * 64;      // 2^22 (16MB)
static constexpr int NUM_BATCH = 8;
static constexpr int NSTAGE    = NUM_BATCH + 1;   // stage s: zero b=s, scatter b=s-1

static constexpr int BLOCK = 256;
// Scatter blocks FIRST (long pole starts at cycle 0): 512 blocks x 256 thr x
// 8 elems = 1,048,576 elems/stage. Zero blocks after: 2048 blocks x 2 float4
// per thread = 16MB/stage.
static constexpr int SBLK = 512;
static constexpr int ZBLK = 2048;
static constexpr int GRID = SBLK + ZBLK;   // 2560

// Runtime-detected layout flags (set by the probe block in stage 0).
__device__ int g_swap;   // 1 if d_in[0] is the indices buffer
__device__ int g_is64;   // 1 if indices are int64

// ---------------------------------------------------------------------------
// Stage kernel with PDL. Stage s zeroes batch s (independent STG.128) and
// scatters batch s-1: 6 independent 16B loads issue PRE-sync (hidden under
// the previous stage's atomic drain), 8 REDs fire post-sync into the zeroed,
// L2-resident batch lines (no DRAM read-modify-write). __ldcs keeps the
// streaming reads from evicting those lines.
// ---------------------------------------------------------------------------
__global__ void __launch_bounds__(BLOCK) stage_kernel(
        const void* __restrict__ p0,
        const void* __restrict__ p1,
        float*      __restrict__ out,
        int stage) {

    cudaTriggerProgrammaticLaunchCompletion();

    if (blockIdx.x >= SBLK) {
        // ---- zero role (2048 blocks): batch = stage ----
        if (stage >= NUM_BATCH) return;
        const long long q = (long long)(blockIdx.x - SBLK);          // [0,2048)
        float4* dst = reinterpret_cast<float4*>(out + ((long long)stage << 22));
        long long t = q * BLOCK + threadIdx.x;                       // [0, 524288)
        const float4 zz = make_float4(0.f, 0.f, 0.f, 0.f);
        dst[t]            = zz;
        dst[t + 524288LL] = zz;
        return;
    }

    // ---- scatter role (512 blocks): batch = stage - 1, 8 elems/thread ----
    if (stage == 0) {
        // Probe (one block): which buffer is indices, and are they int64?
        // Indices are small non-negative ints (< 2^22); normal float bits read
        // as int32 are ~1e9 or negative. int64 < 2^22 has odd words == 0.
        if (blockIdx.x != 0) return;
        const int* a = (const int*)p0;
        const int* b = (const int*)p1;
        int k = threadIdx.x;
        bool ok_a = (a[k] >= 0 && a[k] < (int)PER_BATCH_OUT);
        bool ok_b = (b[k] >= 0 && b[k] < (int)PER_BATCH_OUT);
        int ca = __syncthreads_count(ok_a);
        int cb = __syncthreads_count(ok_b);
        int swap = (ca > cb) ? 1 : 0;
        const int* idx = swap ? a : b;
        int nz = __syncthreads_count(idx[2 * k + 1] != 0);
        if (k == 0) { g_swap = swap; g_is64 = (nz == 0) ? 1 : 0; }
        return;
    }

    const long long b = stage - 1;
    const long long u = (long long)blockIdx.x * BLOCK + threadIdx.x; // [0, 131072)
    const long long i = (b << 20) + (u << 3);                        // first of 8 elems

    // Speculative flag read (stable after stage 0; deterministic on replays).
    int swap_s = __ldcg(&g_swap);
    int is64_s = __ldcg(&g_is64);
    const float* in  = (const float*)(swap_s ? p1 : p0);
    const void*  idx = swap_s ? p0 : p1;

    // Front-batched independent loads (6x16B), pre-sync.
    float4 v0 = __ldcs(reinterpret_cast<const float4*>(in + i));
    float4 v1 = __ldcs(reinterpret_cast<const float4*>(in + i + 4));
    long long j[8];
    if (is64_s) {
        #pragma unroll
        for (int r = 0; r < 4; r++) {
            const longlong2 a = __ldcs(reinterpret_cast<const longlong2*>(idx) + (i >> 1) + r);
            j[2 * r] = a.x; j[2 * r + 1] = a.y;
        }
    } else {
        const int4 a0 = __ldcs(reinterpret_cast<const int4*>(idx) + (i >> 2));
        const int4 a1 = __ldcs(reinterpret_cast<const int4*>(idx) + (i >> 2) + 1);
        j[0] = a0.x; j[1] = a0.y; j[2] = a0.z; j[3] = a0.w;
        j[4] = a1.x; j[5] = a1.y; j[6] = a1.z; j[7] = a1.w;
    }

    // Wait for the previous grid (which zeroed batch b) to complete.
    cudaGridDependencySynchronize();

    // Re-check flags; reload if speculation was wrong (at most once ever,
    // while stage 0's probe was still in flight).
    int swap_c = __ldcg(&g_swap);
    int is64_c = __ldcg(&g_is64);
    if (swap_c != swap_s || is64_c != is64_s) {
        const float* in2  = (const float*)(swap_c ? p1 : p0);
        const void*  idx2 = swap_c ? p0 : p1;
        v0 = __ldcs(reinterpret_cast<const float4*>(in2 + i));
        v1 = __ldcs(reinterpret_cast<const float4*>(in2 + i + 4));
        if (is64_c) {
            #pragma unroll
            for (int r = 0; r < 4; r++) {
                const longlong2 a = __ldcs(reinterpret_cast<const longlong2*>(idx2) + (i >> 1) + r);
                j[2 * r] = a.x; j[2 * r + 1] = a.y;
            }
        } else {
            const int4 a0 = __ldcs(reinterpret_cast<const int4*>(idx2) + (i >> 2));
            const int4 a1 = __ldcs(reinterpret_cast<const int4*>(idx2) + (i >> 2) + 1);
            j[0] = a0.x; j[1] = a0.y; j[2] = a0.z; j[3] = a0.w;
            j[4] = a1.x; j[5] = a1.y; j[6] = a1.z; j[7] = a1.w;
        }
    }

    // 8 REDs into the L2-resident batch slice (all 8 elems same batch).
    float* ob = out + (b << 22);
    const float vv[8] = {v0.x, v0.y, v0.z, v0.w, v1.x, v1.y, v1.z, v1.w};
    #pragma unroll
    for (int r = 0; r < 8; r++)
        if ((unsigned long long)j[r] < (unsigned long long)PER_BATCH_OUT)
            atomicAdd(ob + j[r], vv[r]);
}

extern "C" void kernel_launch(void* const* d_in, const int* in_sizes, int n_in,
                              void* d_out, int out_size) {
    const void* p0 = d_in[0];
    const void* p1 = d_in[1];
    float* out = (float*)d_out;

    cudaLaunchAttribute attr[1];
    attr[0].id = cudaLaunchAttributeProgrammaticStreamSerialization;
    attr[0].val.programmaticStreamSerializationAllowed = 1;

    cudaLaunchConfig_t cfg = {};
    cfg.gridDim  = dim3(GRID, 1, 1);
    cfg.blockDim = dim3(BLOCK, 1, 1);
    cfg.stream = 0;
    cfg.attrs = attr;
    cfg.numAttrs = 1;

    // Stage 0: zero batch 0 + probe. Stages 1..7: zero b + scatter b-1.
    // Stage 8: scatter batch 7 only.
    for (int stage = 0; stage < NSTAGE; stage++) {
        cudaLaunchKernelEx(&cfg, stage_kernel, p0, p1, out, stage);
    }
}

// round 13
// speedup vs baseline: 1.1653x; 1.0388x over previous
#include <cuda_runtime.h>
#include <cuda_bf16.h>
#include <cstdint>

// Problem: B=8, H=128, W=128, C=64, stride 2x2 max-unpool scatter-add.
// inputs  : [8,128,128,64] float32  -> 8,388,608 elements
// indices : [8,128,128,64] int32/int64 -> per-batch flat index into 256*256*64
// output  : [8,256,256,64] float32  -> 33,554,432 elements
static constexpr long long PER_BATCH_OUT = 256LL * 256 * 64;      // 2^22 (16MB)
static constexpr int NUM_BATCH = 8;
static constexpr int NBPS      = 2;                     // batches per stage
static constexpr int NSTAGE    = NUM_BATCH / NBPS + 1;  // 5

static constexpr int BLOCK = 256;
static constexpr int GRID  = 2048;   // uniform fused blocks
// Per stage, per thread (identical op mix to the best R8 kernel):
//   zero  : 4x STG.128 into batches {2s,2s+1}  (2048*256*4 = 2,097,152 float4 = 32MB)
//   scatter: 16B value + 16B index loads, 4 REDs, batches {2s-2,2s-1}
//            (2048*256*4 = 2,097,152 elems)

// Runtime-detected layout flags (set by the probe in stage 0).
__device__ int g_swap;   // 1 if d_in[0] is the indices buffer
__device__ int g_is64;   // 1 if indices are int64

// ---------------------------------------------------------------------------
// Stage kernel, uniform fused roles + PDL, NBPS=2. Every thread does its zero
// slice (independent, fire-and-forget) AND its scatter slice (loads pre-sync
// under the previous stage's atomic drain; REDs post-sync). Zero(b) one
// launch before scatter(b) keeps each 32MB atomic RMW working set L2-resident
// (no DRAM read-modify-write); __ldcs protects those lines from the streams.
// ---------------------------------------------------------------------------
__global__ void __launch_bounds__(BLOCK) stage_kernel(
        const void* __restrict__ p0,
        const void* __restrict__ p1,
        float*      __restrict__ out,
        int stage) {

    cudaTriggerProgrammaticLaunchCompletion();

    const long long t = (long long)blockIdx.x * BLOCK + threadIdx.x;  // [0, 524288)

    // ---- scatter loads (batches 2(s-1)..2s-1), issued FIRST (longest chain).
    long long j0 = -1, j1 = -1, j2 = -1, j3 = -1;
    float4 v = make_float4(0.f, 0.f, 0.f, 0.f);
    int swap_s = 0, is64_s = 0;
    long long i = 0;
    if (stage > 0) {
        swap_s = __ldcg(&g_swap);
        is64_s = __ldcg(&g_is64);
        const float* in  = (const float*)(swap_s ? p1 : p0);
        const void*  idx = swap_s ? p0 : p1;
        const long long tg = ((long long)(NBPS * (stage - 1)) << 18) + t;  // 4-elem group
        i = tg << 2;
        v = __ldcs(reinterpret_cast<const float4*>(in + i));
        if (is64_s) {
            const longlong2 a0 = __ldcs(reinterpret_cast<const longlong2*>(idx) + tg * 2 + 0);
            const longlong2 a1 = __ldcs(reinterpret_cast<const longlong2*>(idx) + tg * 2 + 1);
            j0 = a0.x; j1 = a0.y; j2 = a1.x; j3 = a1.y;
        } else {
            const int4 a = __ldcs(reinterpret_cast<const int4*>(idx) + tg);
            j0 = a.x; j1 = a.y; j2 = a.z; j3 = a.w;
        }
    }

    // ---- zero stores (batches 2s..2s+1): independent, fire-and-forget.
    if (stage < NSTAGE - 1) {
        float4* dst = reinterpret_cast<float4*>(out + ((long long)(NBPS * stage) << 22));
        const float4 zz = make_float4(0.f, 0.f, 0.f, 0.f);
        #pragma unroll
        for (int r = 0; r < 4; r++)
            dst[t + (long long)r * 524288LL] = zz;
    }

    // ---- probe (stage 0, block 0): detect index buffer + width.
    // Indices are small non-negative ints (< 2^22); normal float bits read as
    // int32 are ~1e9 or negative. int64 < 2^22 has all odd 32-bit words == 0.
    if (stage == 0) {
        if (blockIdx.x == 0) {
            const int* a  = (const int*)p0;
            const int* bb = (const int*)p1;
            int k = threadIdx.x;
            bool ok_a = (a[k]  >= 0 && a[k]  < (int)PER_BATCH_OUT);
            bool ok_b = (bb[k] >= 0 && bb[k] < (int)PER_BATCH_OUT);
            int ca = __syncthreads_count(ok_a);
            int cb = __syncthreads_count(ok_b);
            int swap = (ca > cb) ? 1 : 0;
            const int* idx = swap ? a : bb;
            int nz = __syncthreads_count(idx[2 * k + 1] != 0);
            if (k == 0) { g_swap = swap; g_is64 = (nz == 0) ? 1 : 0; }
        }
        return;
    }

    // ---- wait for previous grid (zero of these batches + probe).
    cudaGridDependencySynchronize();

    // Re-check flags; reload if the speculation was wrong (at most once ever,
    // while stage 0's probe was still in flight; deterministic on replays).
    {
        int swap_c = __ldcg(&g_swap);
        int is64_c = __ldcg(&g_is64);
        if (swap_c != swap_s || is64_c != is64_s) {
            const float* in2  = (const float*)(swap_c ? p1 : p0);
            const void*  idx2 = swap_c ? p0 : p1;
            const long long tg = i >> 2;
            v = __ldcs(reinterpret_cast<const float4*>(in2 + i));
            if (is64_c) {
                const longlong2 a0 = __ldcs(reinterpret_cast<const longlong2*>(idx2) + tg * 2 + 0);
                const longlong2 a1 = __ldcs(reinterpret_cast<const longlong2*>(idx2) + tg * 2 + 1);
                j0 = a0.x; j1 = a0.y; j2 = a1.x; j3 = a1.y;
            } else {
                const int4 a = __ldcs(reinterpret_cast<const int4*>(idx2) + tg);
                j0 = a.x; j1 = a.y; j2 = a.z; j3 = a.w;
            }
        }
    }

    // ---- scatter atomics (REDG; bounds-guarded). All 4 elems share a batch.
    float* ob = out + ((i >> 20) << 22);
    if ((unsigned long long)j0 < (unsigned long long)PER_BATCH_OUT) atomicAdd(ob + j0, v.x);
    if ((unsigned long long)j1 < (unsigned long long)PER_BATCH_OUT) atomicAdd(ob + j1, v.y);
    if ((unsigned long long)j2 < (unsigned long long)PER_BATCH_OUT) atomicAdd(ob + j2, v.z);
    if ((unsigned long long)j3 < (unsigned long long)PER_BATCH_OUT) atomicAdd(ob + j3, v.w);
}

extern "C" void kernel_launch(void* const* d_in, const int* in_sizes, int n_in,
                              void* d_out, int out_size) {
    const void* p0 = d_in[0];
    const void* p1 = d_in[1];
    float* out = (float*)d_out;

    cudaLaunchAttribute attr[1];
    attr[0].id = cudaLaunchAttributeProgrammaticStreamSerialization;
    attr[0].val.programmaticStreamSerializationAllowed = 1;

    cudaLaunchConfig_t cfg = {};
    cfg.gridDim  = dim3(GRID, 1, 1);
    cfg.blockDim = dim3(BLOCK, 1, 1);
    cfg.stream = 0;
    cfg.attrs = attr;
    cfg.numAttrs = 1;

    // Stage 0: zero batches {0,1} + probe. Stages 1..3: zero {2s,2s+1} +
    // scatter {2s-2,2s-1}. Stage 4: scatter {6,7} only.
    for (int stage = 0; stage < NSTAGE; stage++) {
        cudaLaunchKernelEx(&cfg, stage_kernel, p0, p1, out, stage);
    }
}

// round 14
// speedup vs baseline: 1.1683x; 1.0026x over previous
#include <cuda_runtime.h>
#include <cuda_bf16.h>
#include <cstdint>

// Problem: B=8, H=128, W=128, C=64, stride 2x2 max-unpool scatter-add.
// inputs  : [8,128,128,64] float32  -> 8,388,608 elements
// indices : [8,128,128,64] int32/int64 -> per-batch flat index into 256*256*64
// output  : [8,256,256,64] float32  -> 33,554,432 elements
static constexpr long long PER_BATCH_OUT = 256LL * 256 * 64;      // 2^22 (16MB)
static constexpr int NUM_BATCH = 8;
static constexpr int NSTAGE    = NUM_BATCH + 1;   // stage s: zero b=s, scatter b=s-1

static constexpr int BLOCK = 256;
// Scatter blocks FIRST: 1024 blocks x 256 thr x 4 elems = 1,048,576 elems.
// Zero blocks: 1024 blocks x one 16KB TMA bulk store = 16MB.
static constexpr int SBLK = 1024;
static constexpr int ZBLK = 1024;
static constexpr int GRID = SBLK + ZBLK;   // 2048

static constexpr int TILE_BYTES = 16384;   // 16KB SMEM zero tile per zero block

// Runtime-detected layout flags (set by the probe block in stage 0).
__device__ int g_swap;   // 1 if d_in[0] is the indices buffer
__device__ int g_is64;   // 1 if indices are int64

// ---------------------------------------------------------------------------
// Stage kernel with PDL. Stage s zeroes batch s via ONE cp.async.bulk 16KB
// store per zero block (async proxy — zero GMEM writes never touch the LSU,
// freeing its issue slots for the scatter's LDGs + REDs) and scatters batch
// s-1 (16B loads pre-sync under the previous stage's atomic drain; REDs
// post-sync into the zeroed, L2-resident batch lines). __ldcs keeps the
// streams from evicting those lines.
// ---------------------------------------------------------------------------
__global__ void __launch_bounds__(BLOCK) stage_kernel(
        const void* __restrict__ p0,
        const void* __restrict__ p1,
        float*      __restrict__ out,
        int stage) {

    cudaTriggerProgrammaticLaunchCompletion();

    __shared__ alignas(128) float4 ztile[TILE_BYTES / 16];

    if (blockIdx.x >= SBLK) {
        // ---- zero role (1024 blocks): batch = stage, 16KB each via TMA ----
        if (stage >= NUM_BATCH) return;
        const long long q = (long long)(blockIdx.x - SBLK);         // [0,1024)
        // Zero the SMEM tile: 4x STS.128/thread (crossbar only, cheap).
        const float4 zz = make_float4(0.f, 0.f, 0.f, 0.f);
        #pragma unroll
        for (int r = 0; r < 4; r++)
            ztile[threadIdx.x + r * BLOCK] = zz;
        asm volatile("fence.proxy.async.shared::cta;" ::: "memory");
        __syncthreads();

        if (threadIdx.x == 0) {
            uint32_t saddr;
            asm("{ .reg .u64 t; cvta.to.shared.u64 t, %1; cvt.u32.u64 %0, t; }"
                : "=r"(saddr) : "l"(ztile));
            char* dst = reinterpret_cast<char*>(out + ((long long)stage << 22))
                        + q * TILE_BYTES;
            asm volatile(
                "cp.async.bulk.global.shared::cta.bulk_group [%0], [%1], %2;"
                :: "l"(dst), "r"(saddr), "n"(TILE_BYTES) : "memory");
            asm volatile("cp.async.bulk.commit_group;" ::: "memory");
            asm volatile("cp.async.bulk.wait_group 0;" ::: "memory");
        }
        return;
    }

    // ---- scatter role (1024 blocks): batch = stage - 1, 4 elems/thread ----
    if (stage == 0) {
        // Probe (one block): which buffer is indices, and are they int64?
        // Indices are small non-negative ints (< 2^22); normal float bits
        // read as int32 are ~1e9 or negative. int64 < 2^22 has odd words 0.
        if (blockIdx.x != 0) return;
        const int* a = (const int*)p0;
        const int* b = (const int*)p1;
        int k = threadIdx.x;
        bool ok_a = (a[k] >= 0 && a[k] < (int)PER_BATCH_OUT);
        bool ok_b = (b[k] >= 0 && b[k] < (int)PER_BATCH_OUT);
        int ca = __syncthreads_count(ok_a);
        int cb = __syncthreads_count(ok_b);
        int swap = (ca > cb) ? 1 : 0;
        const int* idx = swap ? a : b;
        int nz = __syncthreads_count(idx[2 * k + 1] != 0);
        if (k == 0) { g_swap = swap; g_is64 = (nz == 0) ? 1 : 0; }
        return;
    }

    const long long b  = stage - 1;
    const long long u  = (long long)blockIdx.x * BLOCK + threadIdx.x; // [0, 262144)
    const long long tg = (b << 18) + u;               // global 4-elem group id
    const long long i  = tg << 2;

    // Speculative flag read (stable after stage 0; deterministic on replays).
    int swap_s = __ldcg(&g_swap);
    int is64_s = __ldcg(&g_is64);
    const float* in  = (const float*)(swap_s ? p1 : p0);
    const void*  idx = swap_s ? p0 : p1;

    // Front-batched independent loads, pre-sync (hidden under prev drain).
    float4 v = __ldcs(reinterpret_cast<const float4*>(in + i));
    long long j0, j1, j2, j3;
    if (is64_s) {
        const longlong2 a0 = __ldcs(reinterpret_cast<const longlong2*>(idx) + tg * 2 + 0);
        const longlong2 a1 = __ldcs(reinterpret_cast<const longlong2*>(idx) + tg * 2 + 1);
        j0 = a0.x; j1 = a0.y; j2 = a1.x; j3 = a1.y;
    } else {
        const int4 a = __ldcs(reinterpret_cast<const int4*>(idx) + tg);
        j0 = a.x; j1 = a.y; j2 = a.z; j3 = a.w;
    }

    // Wait for the previous grid (zero(b) TMA stores + probe) to complete.
    cudaGridDependencySynchronize();

    // Re-check flags; reload if speculation was wrong (at most once ever,
    // while stage 0's probe was still in flight).
    int swap_c = __ldcg(&g_swap);
    int is64_c = __ldcg(&g_is64);
    if (swap_c != swap_s || is64_c != is64_s) {
        const float* in2  = (const float*)(swap_c ? p1 : p0);
        const void*  idx2 = swap_c ? p0 : p1;
        v = __ldcs(reinterpret_cast<const float4*>(in2 + i));
        if (is64_c) {
            const longlong2 a0 = __ldcs(reinterpret_cast<const longlong2*>(idx2) + tg * 2 + 0);
            const longlong2 a1 = __ldcs(reinterpret_cast<const longlong2*>(idx2) + tg * 2 + 1);
            j0 = a0.x; j1 = a0.y; j2 = a1.x; j3 = a1.y;
        } else {
            const int4 a = __ldcs(reinterpret_cast<const int4*>(idx2) + tg);
            j0 = a.x; j1 = a.y; j2 = a.z; j3 = a.w;
        }
    }

    float* ob = out + (b << 22);   // batch base (all 4 elems same batch)
    if ((unsigned long long)j0 < (unsigned long long)PER_BATCH_OUT) atomicAdd(ob + j0, v.x);
    if ((unsigned long long)j1 < (unsigned long long)PER_BATCH_OUT) atomicAdd(ob + j1, v.y);
    if ((unsigned long long)j2 < (unsigned long long)PER_BATCH_OUT) atomicAdd(ob + j2, v.z);
    if ((unsigned long long)j3 < (unsigned long long)PER_BATCH_OUT) atomicAdd(ob + j3, v.w);
}

extern "C" void kernel_launch(void* const* d_in, const int* in_sizes, int n_in,
                              void* d_out, int out_size) {
    const void* p0 = d_in[0];
    const void* p1 = d_in[1];
    float* out = (float*)d_out;

    cudaLaunchAttribute attr[1];
    attr[0].id = cudaLaunchAttributeProgrammaticStreamSerialization;
    attr[0].val.programmaticStreamSerializationAllowed = 1;

    cudaLaunchConfig_t cfg = {};
    cfg.gridDim  = dim3(GRID, 1, 1);
    cfg.blockDim = dim3(BLOCK, 1, 1);
    cfg.stream = 0;
    cfg.attrs = attr;
    cfg.numAttrs = 1;

    // Stage 0: zero batch 0 + probe. Stages 1..7: zero b + scatter b-1.
    // Stage 8: scatter batch 7 only.
    for (int stage = 0; stage < NSTAGE; stage++) {
        cudaLaunchKernelEx(&cfg, stage_kernel, p0, p1, out, stage);
    }
}